// round 4
// baseline (speedup 1.0000x reference)
#include <cuda_runtime.h>
#include <math.h>

// Problem constants
#define BATCH 2
#define SEQ 2048
#define DMODEL 1024
#define NHEADS 16
#define HDIM 64
#define MTOT (BATCH * SEQ)            // 4096 rows of x
#define OUT_ELEMS ((size_t)MTOT * DMODEL)          // 4,194,304
#define ATTN_ROW SEQ                                // 2048
#define ATTN_PER_HEAD ((size_t)SEQ * SEQ)           // 1<<22

// Scratch (allocation-free rule: __device__ globals)
__device__ float g_q[MTOT * DMODEL];
__device__ float g_k[MTOT * DMODEL];
__device__ float g_v[MTOT * DMODEL];
__device__ float g_ctx[MTOT * DMODEL];

// ---------------- Tiled GEMM: C[M,N] = A[M,K] @ B[K,N] + bias[N] ----------------
#define BM 64
#define BN 64
#define BK 16
// 16x16 threads, each computes a 4x4 micro-tile.

__global__ void gemm_bias(const float* __restrict__ A, const float* __restrict__ B,
                          const float* __restrict__ bias, float* __restrict__ C,
                          int M, int N, int K) {
    __shared__ float As[BM][BK + 1];
    __shared__ float Bs[BK][BN + 1];

    int tx = threadIdx.x;        // 0..15
    int ty = threadIdx.y;        // 0..15
    int tid = ty * 16 + tx;      // 0..255
    int n0 = blockIdx.x * BN;
    int m0 = blockIdx.y * BM;

    float acc[4][4];
#pragma unroll
    for (int i = 0; i < 4; i++)
#pragma unroll
        for (int j = 0; j < 4; j++) acc[i][j] = 0.f;

    for (int k0 = 0; k0 < K; k0 += BK) {
        // Load A tile: 64x16 = 1024 elems, 4 per thread
#pragma unroll
        for (int t = 0; t < 4; t++) {
            int idx = tid + t * 256;
            int r = idx / BK, c = idx % BK;
            As[r][c] = A[(size_t)(m0 + r) * K + (k0 + c)];
        }
        // Load B tile: 16x64 = 1024 elems
#pragma unroll
        for (int t = 0; t < 4; t++) {
            int idx = tid + t * 256;
            int r = idx / BN, c = idx % BN;
            Bs[r][c] = B[(size_t)(k0 + r) * N + (n0 + c)];
        }
        __syncthreads();

#pragma unroll
        for (int kk = 0; kk < BK; kk++) {
            float a[4], b[4];
#pragma unroll
            for (int i = 0; i < 4; i++) a[i] = As[ty * 4 + i][kk];
#pragma unroll
            for (int j = 0; j < 4; j++) b[j] = Bs[kk][tx * 4 + j];
#pragma unroll
            for (int i = 0; i < 4; i++)
#pragma unroll
                for (int j = 0; j < 4; j++) acc[i][j] = fmaf(a[i], b[j], acc[i][j]);
        }
        __syncthreads();
    }

#pragma unroll
    for (int i = 0; i < 4; i++) {
        int m = m0 + ty * 4 + i;
#pragma unroll
        for (int j = 0; j < 4; j++) {
            int n = n0 + tx * 4 + j;
            C[(size_t)m * N + n] = acc[i][j] + bias[n];
        }
    }
}

// ---------------- Scores: S[b,h,q,k] = (Q_bh @ K_bh^T) * scale ----------------
// Q,K layout: [b, L, h, d] flattened as [MTOT, DMODEL]; head slice stride DMODEL.
__global__ void scores_kernel(const float* __restrict__ Q, const float* __restrict__ Km,
                              float* __restrict__ attn) {
    __shared__ float Qs[BM][BK + 1];
    __shared__ float Ks[BN][BK + 1];

    int tx = threadIdx.x, ty = threadIdx.y;
    int tid = ty * 16 + tx;
    int qm0 = blockIdx.x * BM;   // query rows
    int kn0 = blockIdx.y * BN;   // key rows (score cols)
    int z = blockIdx.z;          // b*NHEADS + h
    int b = z / NHEADS, h = z % NHEADS;

    const float* Qb = Q + (size_t)b * SEQ * DMODEL + h * HDIM;
    const float* Kb = Km + (size_t)b * SEQ * DMODEL + h * HDIM;

    float acc[4][4];
#pragma unroll
    for (int i = 0; i < 4; i++)
#pragma unroll
        for (int j = 0; j < 4; j++) acc[i][j] = 0.f;

    for (int k0 = 0; k0 < HDIM; k0 += BK) {
#pragma unroll
        for (int t = 0; t < 4; t++) {
            int idx = tid + t * 256;
            int r = idx / BK, c = idx % BK;
            Qs[r][c] = Qb[(size_t)(qm0 + r) * DMODEL + (k0 + c)];
            Ks[r][c] = Kb[(size_t)(kn0 + r) * DMODEL + (k0 + c)];
        }
        __syncthreads();

#pragma unroll
        for (int kk = 0; kk < BK; kk++) {
            float a[4], bb[4];
#pragma unroll
            for (int i = 0; i < 4; i++) a[i] = Qs[ty * 4 + i][kk];
#pragma unroll
            for (int j = 0; j < 4; j++) bb[j] = Ks[tx * 4 + j][kk];
#pragma unroll
            for (int i = 0; i < 4; i++)
#pragma unroll
                for (int j = 0; j < 4; j++) acc[i][j] = fmaf(a[i], bb[j], acc[i][j]);
        }
        __syncthreads();
    }

    const float scale = 0.125f;  // 1/sqrt(64)
    float* S = attn + (size_t)z * ATTN_PER_HEAD;
#pragma unroll
    for (int i = 0; i < 4; i++) {
        int q = qm0 + ty * 4 + i;
#pragma unroll
        for (int j = 0; j < 4; j++) {
            int k = kn0 + tx * 4 + j;
            S[(size_t)q * SEQ + k] = acc[i][j] * scale;
        }
    }
}

// ---------------- Row softmax over last dim (2048), in place ----------------
__global__ void softmax_rows(float* __restrict__ attn) {
    size_t row = blockIdx.x;
    float* p = attn + row * (size_t)SEQ;
    int t = threadIdx.x;                       // 256 threads
    __shared__ float red[256];

    // max
    float m = -INFINITY;
    for (int i = t; i < SEQ; i += 256) m = fmaxf(m, p[i]);
    red[t] = m;
    __syncthreads();
    for (int s = 128; s > 0; s >>= 1) {
        if (t < s) red[t] = fmaxf(red[t], red[t + s]);
        __syncthreads();
    }
    float rmax = red[0];
    __syncthreads();

    // exp + sum
    float sum = 0.f;
    for (int i = t; i < SEQ; i += 256) {
        float e = __expf(p[i] - rmax);
        p[i] = e;
        sum += e;
    }
    red[t] = sum;
    __syncthreads();
    for (int s = 128; s > 0; s >>= 1) {
        if (t < s) red[t] += red[t + s];
        __syncthreads();
    }
    float inv = 1.f / red[0];
    __syncthreads();

    for (int i = t; i < SEQ; i += 256) p[i] *= inv;
}

// ---------------- ctx[b,q,h,:] = attn[b,h,q,:] @ V[b,:,h,:] ----------------
__global__ void av_kernel(const float* __restrict__ attn, const float* __restrict__ V,
                          float* __restrict__ ctx) {
    __shared__ float As[BM][BK + 1];   // attn tile 64x16
    __shared__ float Bs[BK][BN + 1];   // V tile 16x64

    int tx = threadIdx.x, ty = threadIdx.y;
    int tid = ty * 16 + tx;
    int m0 = blockIdx.y * BM;          // query rows
    int z = blockIdx.z;
    int b = z / NHEADS, h = z % NHEADS;

    const float* A = attn + (size_t)z * ATTN_PER_HEAD;
    const float* Vb = V + (size_t)b * SEQ * DMODEL + h * HDIM;

    float acc[4][4];
#pragma unroll
    for (int i = 0; i < 4; i++)
#pragma unroll
        for (int j = 0; j < 4; j++) acc[i][j] = 0.f;

    for (int k0 = 0; k0 < SEQ; k0 += BK) {
#pragma unroll
        for (int t = 0; t < 4; t++) {
            int idx = tid + t * 256;
            int r = idx / BK, c = idx % BK;
            As[r][c] = A[(size_t)(m0 + r) * SEQ + (k0 + c)];
        }
        // V tile: 16 x 64 (BN == HDIM)
        {
            int r = tid / BN, c = tid % BN;   // 256 threads cover 4 rows each pass
#pragma unroll
            for (int t = 0; t < 4; t++)
                Bs[r + t * 4][c] = Vb[(size_t)(k0 + r + t * 4) * DMODEL + c];
        }
        __syncthreads();

#pragma unroll
        for (int kk = 0; kk < BK; kk++) {
            float a[4], bb[4];
#pragma unroll
            for (int i = 0; i < 4; i++) a[i] = As[ty * 4 + i][kk];
#pragma unroll
            for (int j = 0; j < 4; j++) bb[j] = Bs[kk][tx * 4 + j];
#pragma unroll
            for (int i = 0; i < 4; i++)
#pragma unroll
                for (int j = 0; j < 4; j++) acc[i][j] = fmaf(a[i], bb[j], acc[i][j]);
        }
        __syncthreads();
    }

    float* Cb = ctx + (size_t)b * SEQ * DMODEL + h * HDIM;
#pragma unroll
    for (int i = 0; i < 4; i++) {
        int m = m0 + ty * 4 + i;
#pragma unroll
        for (int j = 0; j < 4; j++) {
            int n = tx * 4 + j;   // 0..63 within head
            Cb[(size_t)m * DMODEL + n] = acc[i][j];
        }
    }
}

extern "C" void kernel_launch(void* const* d_in, const int* in_sizes, int n_in,
                              void* d_out, int out_size) {
    const float* x   = (const float*)d_in[0];
    const float* w_q = (const float*)d_in[1];
    const float* b_q = (const float*)d_in[2];
    const float* w_k = (const float*)d_in[3];
    const float* b_k = (const float*)d_in[4];
    const float* w_v = (const float*)d_in[5];
    const float* b_v = (const float*)d_in[6];
    const float* w_o = (const float*)d_in[7];
    const float* b_o = (const float*)d_in[8];

    float* out  = (float*)d_out;
    float* attn = out + OUT_ELEMS;

    float *q, *k, *v, *ctx;
    cudaGetSymbolAddress((void**)&q,   g_q);
    cudaGetSymbolAddress((void**)&k,   g_k);
    cudaGetSymbolAddress((void**)&v,   g_v);
    cudaGetSymbolAddress((void**)&ctx, g_ctx);

    dim3 blk(16, 16);

    // QKV projections: [4096,1024] @ [1024,1024]
    dim3 g1(DMODEL / BN, MTOT / BM);
    gemm_bias<<<g1, blk>>>(x, w_q, b_q, q, MTOT, DMODEL, DMODEL);
    gemm_bias<<<g1, blk>>>(x, w_k, b_k, k, MTOT, DMODEL, DMODEL);
    gemm_bias<<<g1, blk>>>(x, w_v, b_v, v, MTOT, DMODEL, DMODEL);

    // Scores: per (b,h) 2048x2048 = QK^T * scale
    dim3 g2(SEQ / BM, SEQ / BN, BATCH * NHEADS);
    scores_kernel<<<g2, blk>>>(q, k, attn);

    // Softmax over rows
    softmax_rows<<<BATCH * NHEADS * SEQ, 256>>>(attn);

    // ctx = attn @ V
    dim3 g3(1, SEQ / BM, BATCH * NHEADS);
    av_kernel<<<g3, blk>>>(attn, v, ctx);

    // out = ctx @ w_o + b_o
    gemm_bias<<<g1, blk>>>(ctx, w_o, b_o, out, MTOT, DMODEL, DMODEL);
}

// round 6
// speedup vs baseline: 3.9722x; 3.9722x over previous
#include <cuda_runtime.h>
#include <math.h>

// Problem constants
#define BATCH 2
#define SEQ 2048
#define DMODEL 1024
#define NHEADS 16
#define HDIM 64
#define MTOT (BATCH * SEQ)                 // 4096
#define OUT_ELEMS ((size_t)MTOT * DMODEL)  // 4,194,304
#define APH ((size_t)SEQ * SEQ)            // per-head attn elems

// Scratch (allocation-free rule: __device__ globals)
__device__ float g_q[MTOT * DMODEL];
__device__ float g_k[MTOT * DMODEL];
__device__ float g_v[MTOT * DMODEL];
__device__ float g_ctx[MTOT * DMODEL];

// ---------- tf32 helpers ----------
__device__ __forceinline__ unsigned f2t(float x) {
    unsigned u;
    asm("cvt.rna.tf32.f32 %0, %1;" : "=r"(u) : "f"(x));
    return u;
}

__device__ __forceinline__ void mma8(float* d, const unsigned* a, const unsigned* b) {
    asm volatile(
        "mma.sync.aligned.m16n8k8.row.col.f32.tf32.tf32.f32 "
        "{%0,%1,%2,%3}, {%4,%5,%6,%7}, {%8,%9}, {%0,%1,%2,%3};\n"
        : "+f"(d[0]), "+f"(d[1]), "+f"(d[2]), "+f"(d[3])
        : "r"(a[0]), "r"(a[1]), "r"(a[2]), "r"(a[3]), "r"(b[0]), "r"(b[1]));
}

#define LDA 132    // 128 + 4 pad (k-major smem row stride, in floats)
#define LDBV 68    // 64 + 4 pad for AV's V tile
#define PBK 16     // K-chunk per smem stage

// ======================================================================
// GEMM: C[M,N] = A[M,K] @ B[K,N] + bias[N]    (tile 128x128x16, 8 warps)
// ======================================================================
__global__ __launch_bounds__(256) void gemm_bias_tc(
    const float* __restrict__ A, const float* __restrict__ B,
    const float* __restrict__ bias, float* __restrict__ C,
    int M, int N, int K)
{
    __shared__ unsigned sA[2][PBK * LDA];
    __shared__ unsigned sB[2][PBK * LDA];

    int tid = threadIdx.x, lane = tid & 31, wid = tid >> 5;
    int grp = lane >> 2, tig = lane & 3;
    int m0 = blockIdx.y * 128, n0 = blockIdx.x * 128;
    int wm = (wid >> 2) * 64, wn = (wid & 3) * 32;

    int ar = tid >> 2, ac = (tid & 3) * 4;   // A tile: 128 rows x 16 cols
    int br = tid >> 5, bc = (tid & 31) * 4;  // B tile: 16 rows x 128 cols

    float acc[4][4][4] = {};
    float4 ra[2], rb[2];

    auto ldg = [&](int k0) {
        ra[0] = *(const float4*)&A[(size_t)(m0 + ar) * K + k0 + ac];
        ra[1] = *(const float4*)&A[(size_t)(m0 + ar + 64) * K + k0 + ac];
        rb[0] = *(const float4*)&B[(size_t)(k0 + br) * N + n0 + bc];
        rb[1] = *(const float4*)&B[(size_t)(k0 + br + 8) * N + n0 + bc];
    };
    auto sts = [&](int bf) {
        unsigned* pa = sA[bf];
        unsigned* pb = sB[bf];
#pragma unroll
        for (int p = 0; p < 2; p++) {
            const float* f = (const float*)&ra[p];
            const float* g = (const float*)&rb[p];
#pragma unroll
            for (int j = 0; j < 4; j++) {
                pa[(ac + j) * LDA + ar + p * 64] = f2t(f[j]);     // transposed (k-major)
                pb[(br + p * 8) * LDA + bc + j] = f2t(g[j]);      // direct (k-major)
            }
        }
    };

    int NIT = K / PBK;
    ldg(0);
    sts(0);
    __syncthreads();

    for (int it = 0; it < NIT; ++it) {
        int cur = it & 1;
        if (it + 1 < NIT) ldg((it + 1) * PBK);
#pragma unroll
        for (int ks = 0; ks < 2; ks++) {
            unsigned af[4][4], bfm[4][2];
            const unsigned* sa = sA[cur];
            const unsigned* sb = sB[cur];
#pragma unroll
            for (int mi = 0; mi < 4; mi++) {
                int mb = wm + mi * 16 + grp;
                af[mi][0] = sa[(ks * 8 + tig) * LDA + mb];
                af[mi][1] = sa[(ks * 8 + tig) * LDA + mb + 8];
                af[mi][2] = sa[(ks * 8 + tig + 4) * LDA + mb];
                af[mi][3] = sa[(ks * 8 + tig + 4) * LDA + mb + 8];
            }
#pragma unroll
            for (int ni = 0; ni < 4; ni++) {
                int nb = wn + ni * 8 + grp;
                bfm[ni][0] = sb[(ks * 8 + tig) * LDA + nb];
                bfm[ni][1] = sb[(ks * 8 + tig + 4) * LDA + nb];
            }
#pragma unroll
            for (int mi = 0; mi < 4; mi++)
#pragma unroll
                for (int ni = 0; ni < 4; ni++) mma8(acc[mi][ni], af[mi], bfm[ni]);
        }
        if (it + 1 < NIT) sts(cur ^ 1);
        __syncthreads();
    }

#pragma unroll
    for (int mi = 0; mi < 4; mi++) {
        int row = m0 + wm + mi * 16 + grp;
#pragma unroll
        for (int ni = 0; ni < 4; ni++) {
            int col = n0 + wn + ni * 8 + 2 * tig;
            float b0 = bias[col], b1 = bias[col + 1];
            C[(size_t)row * N + col]           = acc[mi][ni][0] + b0;
            C[(size_t)row * N + col + 1]       = acc[mi][ni][1] + b1;
            C[(size_t)(row + 8) * N + col]     = acc[mi][ni][2] + b0;
            C[(size_t)(row + 8) * N + col + 1] = acc[mi][ni][3] + b1;
        }
    }
}

// ======================================================================
// Scores: attn[z,q,k] = (Q_z @ K_z^T) * 0.125     tile 128x128, K=64
// Q,K layout: [b, L, h*64+d]; head slice row stride = DMODEL
// ======================================================================
__global__ __launch_bounds__(256) void scores_tc(
    const float* __restrict__ Q, const float* __restrict__ Km,
    float* __restrict__ attn)
{
    __shared__ unsigned sA[2][PBK * LDA];
    __shared__ unsigned sB[2][PBK * LDA];

    int tid = threadIdx.x, lane = tid & 31, wid = tid >> 5;
    int grp = lane >> 2, tig = lane & 3;
    int q0 = blockIdx.y * 128, n0 = blockIdx.x * 128;
    int z = blockIdx.z, b = z / NHEADS, h = z % NHEADS;
    int wm = (wid >> 2) * 64, wn = (wid & 3) * 32;
    int ar = tid >> 2, ac = (tid & 3) * 4;

    const float* Qb = Q + (size_t)b * SEQ * DMODEL + h * HDIM;
    const float* Kb = Km + (size_t)b * SEQ * DMODEL + h * HDIM;

    float acc[4][4][4] = {};
    float4 ra[2], rk[2];

    auto ldg = [&](int k0) {
        ra[0] = *(const float4*)&Qb[(size_t)(q0 + ar) * DMODEL + k0 + ac];
        ra[1] = *(const float4*)&Qb[(size_t)(q0 + ar + 64) * DMODEL + k0 + ac];
        rk[0] = *(const float4*)&Kb[(size_t)(n0 + ar) * DMODEL + k0 + ac];
        rk[1] = *(const float4*)&Kb[(size_t)(n0 + ar + 64) * DMODEL + k0 + ac];
    };
    auto sts = [&](int bf) {
        unsigned* pa = sA[bf];
        unsigned* pb = sB[bf];
#pragma unroll
        for (int p = 0; p < 2; p++) {
            const float* f = (const float*)&ra[p];
            const float* g = (const float*)&rk[p];
#pragma unroll
            for (int j = 0; j < 4; j++) {
                pa[(ac + j) * LDA + ar + p * 64] = f2t(f[j]);
                pb[(ac + j) * LDA + ar + p * 64] = f2t(g[j]);
            }
        }
    };

    const int NIT = HDIM / PBK;  // 4
    ldg(0);
    sts(0);
    __syncthreads();

    for (int it = 0; it < NIT; ++it) {
        int cur = it & 1;
        if (it + 1 < NIT) ldg((it + 1) * PBK);
#pragma unroll
        for (int ks = 0; ks < 2; ks++) {
            unsigned af[4][4], bfm[4][2];
            const unsigned* sa = sA[cur];
            const unsigned* sb = sB[cur];
#pragma unroll
            for (int mi = 0; mi < 4; mi++) {
                int mb = wm + mi * 16 + grp;
                af[mi][0] = sa[(ks * 8 + tig) * LDA + mb];
                af[mi][1] = sa[(ks * 8 + tig) * LDA + mb + 8];
                af[mi][2] = sa[(ks * 8 + tig + 4) * LDA + mb];
                af[mi][3] = sa[(ks * 8 + tig + 4) * LDA + mb + 8];
            }
#pragma unroll
            for (int ni = 0; ni < 4; ni++) {
                int nb = wn + ni * 8 + grp;
                bfm[ni][0] = sb[(ks * 8 + tig) * LDA + nb];
                bfm[ni][1] = sb[(ks * 8 + tig + 4) * LDA + nb];
            }
#pragma unroll
            for (int mi = 0; mi < 4; mi++)
#pragma unroll
                for (int ni = 0; ni < 4; ni++) mma8(acc[mi][ni], af[mi], bfm[ni]);
        }
        if (it + 1 < NIT) sts(cur ^ 1);
        __syncthreads();
    }

    float* S = attn + (size_t)z * APH;
    const float scale = 0.125f;  // 1/sqrt(64)
#pragma unroll
    for (int mi = 0; mi < 4; mi++) {
        int row = q0 + wm + mi * 16 + grp;
#pragma unroll
        for (int ni = 0; ni < 4; ni++) {
            int col = n0 + wn + ni * 8 + 2 * tig;
            S[(size_t)row * SEQ + col]           = acc[mi][ni][0] * scale;
            S[(size_t)row * SEQ + col + 1]       = acc[mi][ni][1] * scale;
            S[(size_t)(row + 8) * SEQ + col]     = acc[mi][ni][2] * scale;
            S[(size_t)(row + 8) * SEQ + col + 1] = acc[mi][ni][3] * scale;
        }
    }
}

// ======================================================================
// Softmax over rows of 2048, register-resident (1 read + 1 write)
// ======================================================================
__global__ __launch_bounds__(256) void softmax_rows(float* __restrict__ attn) {
    size_t row = blockIdx.x;
    float4* p = (float4*)(attn + row * (size_t)SEQ);
    int t = threadIdx.x, lane = t & 31, w = t >> 5;
    __shared__ float red[8];

    float4 v0 = p[t];
    float4 v1 = p[t + 256];

    float m = fmaxf(fmaxf(fmaxf(v0.x, v0.y), fmaxf(v0.z, v0.w)),
                    fmaxf(fmaxf(v1.x, v1.y), fmaxf(v1.z, v1.w)));
#pragma unroll
    for (int o = 16; o; o >>= 1) m = fmaxf(m, __shfl_xor_sync(~0u, m, o));
    if (lane == 0) red[w] = m;
    __syncthreads();
    m = red[0];
#pragma unroll
    for (int i = 1; i < 8; i++) m = fmaxf(m, red[i]);
    __syncthreads();

    v0.x = __expf(v0.x - m); v0.y = __expf(v0.y - m);
    v0.z = __expf(v0.z - m); v0.w = __expf(v0.w - m);
    v1.x = __expf(v1.x - m); v1.y = __expf(v1.y - m);
    v1.z = __expf(v1.z - m); v1.w = __expf(v1.w - m);

    float s = v0.x + v0.y + v0.z + v0.w + v1.x + v1.y + v1.z + v1.w;
#pragma unroll
    for (int o = 16; o; o >>= 1) s += __shfl_xor_sync(~0u, s, o);
    if (lane == 0) red[w] = s;
    __syncthreads();
    s = red[0];
#pragma unroll
    for (int i = 1; i < 8; i++) s += red[i];
    float inv = 1.f / s;

    v0.x *= inv; v0.y *= inv; v0.z *= inv; v0.w *= inv;
    v1.x *= inv; v1.y *= inv; v1.z *= inv; v1.w *= inv;
    p[t] = v0;
    p[t + 256] = v1;
}

// ======================================================================
// AV: ctx[b,q,h*64+n] = attn[z,q,:] @ V[b,:,h*64+n]    tile 128x64, K=2048
// ======================================================================
__global__ __launch_bounds__(256) void av_tc(
    const float* __restrict__ attn, const float* __restrict__ V,
    float* __restrict__ ctx)
{
    __shared__ unsigned sA[2][PBK * LDA];
    __shared__ unsigned sB[2][PBK * LDBV];

    int tid = threadIdx.x, lane = tid & 31, wid = tid >> 5;
    int grp = lane >> 2, tig = lane & 3;
    int m0 = blockIdx.x * 128;
    int z = blockIdx.y, b = z / NHEADS, h = z % NHEADS;
    int wm = (wid >> 1) * 32, wn = (wid & 1) * 32;  // 4x2 warp grid, 32x32 tiles
    int ar = tid >> 2, ac = (tid & 3) * 4;          // A tile 128x16
    int rv = tid >> 4, cv = (tid & 15) * 4;         // V tile 16x64

    const float* Ab = attn + (size_t)z * APH;
    const float* Vb = V + (size_t)b * SEQ * DMODEL + h * HDIM;

    float acc[2][4][4] = {};
    float4 ra[2], rb;

    auto ldg = [&](int k0) {
        ra[0] = *(const float4*)&Ab[(size_t)(m0 + ar) * SEQ + k0 + ac];
        ra[1] = *(const float4*)&Ab[(size_t)(m0 + ar + 64) * SEQ + k0 + ac];
        rb    = *(const float4*)&Vb[(size_t)(k0 + rv) * DMODEL + cv];
    };
    auto sts = [&](int bf) {
        unsigned* pa = sA[bf];
        unsigned* pb = sB[bf];
#pragma unroll
        for (int p = 0; p < 2; p++) {
            const float* f = (const float*)&ra[p];
#pragma unroll
            for (int j = 0; j < 4; j++)
                pa[(ac + j) * LDA + ar + p * 64] = f2t(f[j]);
        }
        const float* g = (const float*)&rb;
#pragma unroll
        for (int j = 0; j < 4; j++) pb[rv * LDBV + cv + j] = f2t(g[j]);
    };

    const int NIT = SEQ / PBK;  // 128
    ldg(0);
    sts(0);
    __syncthreads();

    for (int it = 0; it < NIT; ++it) {
        int cur = it & 1;
        if (it + 1 < NIT) ldg((it + 1) * PBK);
#pragma unroll
        for (int ks = 0; ks < 2; ks++) {
            unsigned af[2][4], bfm[4][2];
            const unsigned* sa = sA[cur];
            const unsigned* sb = sB[cur];
#pragma unroll
            for (int mi = 0; mi < 2; mi++) {
                int mb = wm + mi * 16 + grp;
                af[mi][0] = sa[(ks * 8 + tig) * LDA + mb];
                af[mi][1] = sa[(ks * 8 + tig) * LDA + mb + 8];
                af[mi][2] = sa[(ks * 8 + tig + 4) * LDA + mb];
                af[mi][3] = sa[(ks * 8 + tig + 4) * LDA + mb + 8];
            }
#pragma unroll
            for (int ni = 0; ni < 4; ni++) {
                int nb = wn + ni * 8 + grp;
                bfm[ni][0] = sb[(ks * 8 + tig) * LDBV + nb];
                bfm[ni][1] = sb[(ks * 8 + tig + 4) * LDBV + nb];
            }
#pragma unroll
            for (int mi = 0; mi < 2; mi++)
#pragma unroll
                for (int ni = 0; ni < 4; ni++) mma8(acc[mi][ni], af[mi], bfm[ni]);
        }
        if (it + 1 < NIT) sts(cur ^ 1);
        __syncthreads();
    }

    float* Cb = ctx + (size_t)b * SEQ * DMODEL + h * HDIM;
#pragma unroll
    for (int mi = 0; mi < 2; mi++) {
        int row = m0 + wm + mi * 16 + grp;
#pragma unroll
        for (int ni = 0; ni < 4; ni++) {
            int col = wn + ni * 8 + 2 * tig;
            Cb[(size_t)row * DMODEL + col]           = acc[mi][ni][0];
            Cb[(size_t)row * DMODEL + col + 1]       = acc[mi][ni][1];
            Cb[(size_t)(row + 8) * DMODEL + col]     = acc[mi][ni][2];
            Cb[(size_t)(row + 8) * DMODEL + col + 1] = acc[mi][ni][3];
        }
    }
}

extern "C" void kernel_launch(void* const* d_in, const int* in_sizes, int n_in,
                              void* d_out, int out_size) {
    const float* x   = (const float*)d_in[0];
    const float* w_q = (const float*)d_in[1];
    const float* b_q = (const float*)d_in[2];
    const float* w_k = (const float*)d_in[3];
    const float* b_k = (const float*)d_in[4];
    const float* w_v = (const float*)d_in[5];
    const float* b_v = (const float*)d_in[6];
    const float* w_o = (const float*)d_in[7];
    const float* b_o = (const float*)d_in[8];

    float* out  = (float*)d_out;
    float* attn = out + OUT_ELEMS;

    float *q, *k, *v, *ctx;
    cudaGetSymbolAddress((void**)&q,   g_q);
    cudaGetSymbolAddress((void**)&k,   g_k);
    cudaGetSymbolAddress((void**)&v,   g_v);
    cudaGetSymbolAddress((void**)&ctx, g_ctx);

    // QKV projections: [4096,1024] @ [1024,1024]
    dim3 g1(DMODEL / 128, MTOT / 128);
    gemm_bias_tc<<<g1, 256>>>(x, w_q, b_q, q, MTOT, DMODEL, DMODEL);
    gemm_bias_tc<<<g1, 256>>>(x, w_k, b_k, k, MTOT, DMODEL, DMODEL);
    gemm_bias_tc<<<g1, 256>>>(x, w_v, b_v, v, MTOT, DMODEL, DMODEL);

    // Scores per (b,h): 2048x2048 = QK^T * scale
    dim3 g2(SEQ / 128, SEQ / 128, BATCH * NHEADS);
    scores_tc<<<g2, 256>>>(q, k, attn);

    // Softmax over rows (register-resident)
    softmax_rows<<<BATCH * NHEADS * SEQ, 256>>>(attn);

    // ctx = attn @ V
    dim3 g3(SEQ / 128, BATCH * NHEADS);
    av_tc<<<g3, 256>>>(attn, v, ctx);

    // out = ctx @ w_o + b_o
    gemm_bias_tc<<<g1, 256>>>(ctx, w_o, b_o, out, MTOT, DMODEL, DMODEL);
}